// round 1
// baseline (speedup 1.0000x reference)
#include <cuda_runtime.h>
#include <cuda_bf16.h>
#include <math.h>

#define BATCH   8
#define DIM     512
#define LEN     2048
#define GIN     256
#define NFFT    1024
#define HOP     256
#define WIN     1024
#define OUT_DIM 1026
#define PADP    384
#define KS      5
#define OUTLEN  524288
#define M1      1536
#define MOPAD   1152

__device__ float g_h0[BATCH * DIM * LEN];
__device__ float g_h1[BATCH * M1 * LEN];
__device__ float g_h3[BATCH * OUT_DIM * LEN];
__device__ float g_sri[BATCH * 1024 * LEN];
__device__ float g_frames[BATCH * 1024 * LEN];
__device__ float g_weff1[BATCH * M1 * DIM];
__device__ float g_weff2[BATCH * DIM * M1];
__device__ float g_weffo[BATCH * MOPAD * DIM];
__device__ float g_F[1024 * 1024];
__device__ float g_vin1 [BATCH * DIM * 12];
__device__ float g_vout1[BATCH * 12 * M1];
__device__ float g_vin2 [BATCH * M1 * 12];
__device__ float g_vout2[BATCH * 12 * DIM];
__device__ float g_vino [BATCH * DIM * 16];
__device__ float g_vouto[BATCH * 16 * OUT_DIM];

__global__ void gemv_g_kernel(const float* __restrict__ mat,
                              const float* __restrict__ gvec,
                              float* __restrict__ out, int rows)
{
    int w    = (blockIdx.x * blockDim.x + threadIdx.x) >> 5;
    int lane = threadIdx.x & 31;
    int total = rows * BATCH;
    if (w >= total) return;
    int b = w / rows;
    int o = w - b * rows;
    const float* r = mat + (long)o * GIN;
    const float* g = gvec + (long)b * GIN;
    float s = 0.f;
    #pragma unroll
    for (int i = 0; i < GIN / 32; i++) s += r[lane + 32 * i] * g[lane + 32 * i];
    #pragma unroll
    for (int off = 16; off; off >>= 1) s += __shfl_xor_sync(0xffffffffu, s, off);
    if (lane == 0) out[(long)b * rows + o] = s;
}

__global__ void build_weff_kernel(const float* __restrict__ W,
                                  const float* __restrict__ vin,
                                  const float* __restrict__ vout,
                                  float* __restrict__ weff,
                                  int outch, int inch, int r, int Mpad)
{
    long idx = (long)blockIdx.x * blockDim.x + threadIdx.x;
    long per = (long)Mpad * inch;
    if (idx >= per * BATCH) return;
    int b = (int)(idx / per);
    long rem = idx - (long)b * per;
    int o = (int)(rem / inch);
    int i = (int)(rem - (long)o * inch);
    float v = 0.f;
    if (o < outch) {
        v = W[(long)o * inch + i];
        const float* vi = vin + ((long)b * inch + i) * r;
        const float* vo = vout + (long)b * r * outch + o;
        for (int rr = 0; rr < r; rr++) v += vo[(long)rr * outch] * vi[rr];
    }
    weff[idx] = v;
}

__global__ void dconv_kernel(const float* __restrict__ x,
                             const float* __restrict__ w,
                             const float* __restrict__ bias,
                             float* __restrict__ y)
{
    int idx = blockIdx.x * blockDim.x + threadIdx.x;
    if (idx >= BATCH * DIM * LEN) return;
    int t = idx & (LEN - 1);
    int c = (idx >> 11) & (DIM - 1);
    float acc = bias[c];
    #pragma unroll
    for (int k = 0; k < KS; k++)
        if (t - k >= 0) acc += w[c * KS + k] * x[idx - k];
    y[idx] = acc;
}

__global__ void fill_F_kernel()
{
    int idx = blockIdx.x * blockDim.x + threadIdx.x;
    if (idx >= 1024 * 1024) return;
    int j = idx & 1023;
    int n = idx >> 10;
    float v;
    if (j < 513) {
        int m = (j * n) & 1023;
        v = cospif((float)m * (1.0f / 512.0f));
    } else {
        int k = j - 512;
        int m = (k * n) & 1023;
        v = sinpif((float)m * (1.0f / 512.0f));
    }
    g_F[idx] = v;
}

__global__ void prep_sri_kernel()
{
    int idx = blockIdx.x * blockDim.x + threadIdx.x;
    if (idx >= BATCH * 513 * LEN) return;
    int t = idx & (LEN - 1);
    int k = (idx >> 11) % 513;
    int b = idx / (513 * LEN);
    const float* hb = g_h3 + (long)b * OUT_DIM * LEN;
    float m = hb[(long)k * LEN + t];
    float p = hb[(long)(513 + k) * LEN + t];
    float mag = fminf(expf(m), 100.0f);
    float s, c;
    sincosf(p, &s, &c);
    const float invN = 1.0f / 1024.0f;
    float ck = (k == 0 || k == 512) ? invN : 2.0f * invN;
    float* sb = g_sri + (long)b * 1024 * LEN;
    sb[(long)k * LEN + t] = ck * mag * c;
    if (k >= 1 && k <= 511)
        sb[(long)(512 + k) * LEN + t] = -2.0f * invN * mag * s;
}

__global__ void ola_kernel(const float* __restrict__ frames, float* __restrict__ out)
{
    int idx = blockIdx.x * blockDim.x + threadIdx.x;
    if (idx >= BATCH * OUTLEN) return;
    int b = idx >> 19;
    int pos = idx & (OUTLEN - 1);
    int tpad = pos + PADP;
    int fmax = tpad >> 8; if (fmax > LEN - 1) fmax = LEN - 1;
    int fmin = (tpad - (WIN - 1) + (HOP - 1)) >> 8; if (fmin < 0) fmin = 0;
    const float* fb = frames + (long)b * 1024 * LEN;
    float num = 0.f, den = 0.f;
    for (int f = fmin; f <= fmax; f++) {
        int n = tpad - (f << 8);
        float w = 0.5f - 0.5f * cospif((float)n * (1.0f / 512.0f));
        num += fb[(long)n * LEN + f] * w;
        den += w * w;
    }
    out[idx] = num / den;
}

__global__ __launch_bounds__(256, 2)
void sgemm_kernel(const float* __restrict__ A, const float* __restrict__ B,
                  const float* __restrict__ bias, float* __restrict__ C,
                  int M, int K, int N, int Mc, long aStride, int doGelu)
{
    __shared__ float As[8][128];
    __shared__ float Bs[8][128];

    int b = blockIdx.z;
    const float* Ab = A + (long)b * aStride;
    const float* Bb = B + (long)b * (long)K * N;
    float* Cb = C + (long)b * (long)Mc * N;

    int tid = threadIdx.x;
    int rowBase = blockIdx.y * 128;
    int colBase = blockIdx.x * 128;

    int aRow = tid >> 1;
    int aCol = (tid & 1) << 2;
    int bRow = tid >> 5;
    int bCol = (tid & 31) << 2;

    const float* Aptr = Ab + (long)(rowBase + aRow) * K + aCol;
    const float* Bptr = Bb + (long)bRow * N + colBase + bCol;

    int tx = tid & 15, ty = tid >> 4;

    float acc[8][8];
    #pragma unroll
    for (int i = 0; i < 8; i++)
        #pragma unroll
        for (int j = 0; j < 8; j++) acc[i][j] = 0.f;

    int nIter = K >> 3;
    for (int it = 0; it < nIter; it++) {
        float4 a4 = *reinterpret_cast<const float4*>(Aptr);
        float4 b4 = *reinterpret_cast<const float4*>(Bptr);
        Aptr += 8;
        Bptr += (long)8 * N;
        As[aCol + 0][aRow] = a4.x;
        As[aCol + 1][aRow] = a4.y;
        As[aCol + 2][aRow] = a4.z;
        As[aCol + 3][aRow] = a4.w;
        *reinterpret_cast<float4*>(&Bs[bRow][bCol]) = b4;
        __syncthreads();

        #pragma unroll
        for (int kk = 0; kk < 8; kk++) {
            float ra[8], rb[8];
            float4 t0 = *reinterpret_cast<const float4*>(&As[kk][ty * 8]);
            float4 t1 = *reinterpret_cast<const float4*>(&As[kk][ty * 8 + 4]);
            ra[0] = t0.x; ra[1] = t0.y; ra[2] = t0.z; ra[3] = t0.w;
            ra[4] = t1.x; ra[5] = t1.y; ra[6] = t1.z; ra[7] = t1.w;
            float4 u0 = *reinterpret_cast<const float4*>(&Bs[kk][tx * 8]);
            float4 u1 = *reinterpret_cast<const float4*>(&Bs[kk][tx * 8 + 4]);
            rb[0] = u0.x; rb[1] = u0.y; rb[2] = u0.z; rb[3] = u0.w;
            rb[4] = u1.x; rb[5] = u1.y; rb[6] = u1.z; rb[7] = u1.w;
            #pragma unroll
            for (int i = 0; i < 8; i++)
                #pragma unroll
                for (int j = 0; j < 8; j++)
                    acc[i][j] = fmaf(ra[i], rb[j], acc[i][j]);
        }
        __syncthreads();
    }

    #pragma unroll
    for (int i = 0; i < 8; i++) {
        int row = rowBase + ty * 8 + i;
        if (row >= Mc) continue;
        float bv = bias ? bias[row] : 0.f;
        float v[8];
        #pragma unroll
        for (int j = 0; j < 8; j++) {
            float xv = acc[i][j] + bv;
            if (doGelu) xv = 0.5f * xv * (1.0f + erff(xv * 0.70710678118654752f));
            v[j] = xv;
        }
        float* cp = Cb + (long)row * N + colBase + tx * 8;
        *reinterpret_cast<float4*>(cp)     = make_float4(v[0], v[1], v[2], v[3]);
        *reinterpret_cast<float4*>(cp + 4) = make_float4(v[4], v[5], v[6], v[7]);
    }
}

extern "C" void kernel_launch(void* const* d_in, const int* in_sizes, int n_in,
                              void* d_out, int out_size)
{
    const float* x       = (const float*)d_in[0];
    const float* g_outv  = (const float*)d_in[1];
    const float* dconv_w = (const float*)d_in[2];
    const float* dconv_b = (const float*)d_in[3];
    const float* p1_w    = (const float*)d_in[4];
    const float* p1_b    = (const float*)d_in[5];
    const float* p1_ain  = (const float*)d_in[6];
    const float* p1_aout = (const float*)d_in[7];
    const float* p2_w    = (const float*)d_in[8];
    const float* p2_b    = (const float*)d_in[9];
    const float* p2_ain  = (const float*)d_in[10];
    const float* p2_aout = (const float*)d_in[11];
    const float* out_w   = (const float*)d_in[12];
    const float* out_b   = (const float*)d_in[13];
    const float* out_ain = (const float*)d_in[14];
    const float* out_aout= (const float*)d_in[15];
    float* out = (float*)d_out;

    float *h0, *h1, *h3, *sri, *frames, *weff1, *weff2, *weffo, *Fb;
    float *vin1, *vout1, *vin2, *vout2, *vino, *vouto;
    cudaGetSymbolAddress((void**)&h0, g_h0);
    cudaGetSymbolAddress((void**)&h1, g_h1);
    cudaGetSymbolAddress((void**)&h3, g_h3);
    cudaGetSymbolAddress((void**)&sri, g_sri);
    cudaGetSymbolAddress((void**)&frames, g_frames);
    cudaGetSymbolAddress((void**)&weff1, g_weff1);
    cudaGetSymbolAddress((void**)&weff2, g_weff2);
    cudaGetSymbolAddress((void**)&weffo, g_weffo);
    cudaGetSymbolAddress((void**)&Fb, g_F);
    cudaGetSymbolAddress((void**)&vin1, g_vin1);
    cudaGetSymbolAddress((void**)&vout1, g_vout1);
    cudaGetSymbolAddress((void**)&vin2, g_vin2);
    cudaGetSymbolAddress((void**)&vout2, g_vout2);
    cudaGetSymbolAddress((void**)&vino, g_vino);
    cudaGetSymbolAddress((void**)&vouto, g_vouto);

    fill_F_kernel<<<(1024 * 1024) / 256, 256>>>();

    auto gemvBlocks = [](int rows) { return (rows * BATCH * 32 + 255) / 256; };
    gemv_g_kernel<<<gemvBlocks(DIM * 12), 256>>>(p1_ain,  g_outv, vin1,  DIM * 12);
    gemv_g_kernel<<<gemvBlocks(12 * M1),  256>>>(p1_aout, g_outv, vout1, 12 * M1);
    gemv_g_kernel<<<gemvBlocks(M1 * 12),  256>>>(p2_ain,  g_outv, vin2,  M1 * 12);
    gemv_g_kernel<<<gemvBlocks(12 * DIM), 256>>>(p2_aout, g_outv, vout2, 12 * DIM);
    gemv_g_kernel<<<gemvBlocks(DIM * 16), 256>>>(out_ain, g_outv, vino,  DIM * 16);
    gemv_g_kernel<<<gemvBlocks(16 * OUT_DIM), 256>>>(out_aout, g_outv, vouto, 16 * OUT_DIM);

    {
        long t1 = (long)BATCH * M1 * DIM;
        build_weff_kernel<<<(unsigned)((t1 + 255) / 256), 256>>>(p1_w, vin1, vout1, weff1, M1, DIM, 12, M1);
        long t2 = (long)BATCH * DIM * M1;
        build_weff_kernel<<<(unsigned)((t2 + 255) / 256), 256>>>(p2_w, vin2, vout2, weff2, DIM, M1, 12, DIM);
        long t3 = (long)BATCH * MOPAD * DIM;
        build_weff_kernel<<<(unsigned)((t3 + 255) / 256), 256>>>(out_w, vino, vouto, weffo, OUT_DIM, DIM, 16, MOPAD);
    }

    dconv_kernel<<<(BATCH * DIM * LEN) / 256, 256>>>(x, dconv_w, dconv_b, h0);

    {
        dim3 grid(LEN / 128, M1 / 128, BATCH);
        sgemm_kernel<<<grid, 256>>>(weff1, h0, p1_b, h1, M1, DIM, LEN, M1, (long)M1 * DIM, 1);
    }
    {
        dim3 grid(LEN / 128, DIM / 128, BATCH);
        sgemm_kernel<<<grid, 256>>>(weff2, h1, p2_b, h0, DIM, M1, LEN, DIM, (long)DIM * M1, 1);
    }
    {
        dim3 grid(LEN / 128, MOPAD / 128, BATCH);
        sgemm_kernel<<<grid, 256>>>(weffo, h0, out_b, h3, MOPAD, DIM, LEN, OUT_DIM, (long)MOPAD * DIM, 0);
    }

    prep_sri_kernel<<<(BATCH * 513 * LEN) / 256, 256>>>();

    {
        dim3 grid(LEN / 128, 1024 / 128, BATCH);
        sgemm_kernel<<<grid, 256>>>(Fb, sri, nullptr, frames, 1024, 1024, LEN, 1024, 0L, 0);
    }

    ola_kernel<<<(BATCH * OUTLEN) / 256, 256>>>(frames, out);
}